// round 14
// baseline (speedup 1.0000x reference)
#include <cuda_runtime.h>
#include <cuda_fp16.h>
#include <cstdint>

#define T_TOK 8192
#define D_DIM 1024
#define E_EXP 8
#define I_DIM 3072
#define TRX   16384
#define BM 128
#define BK 64
#define STAGES 3
#define MAXT 144
#define GRID_TILES 136   // max sum ceil(count_e/128)

// ------------------- device scratch (static: no allocation) -------------------
__device__ int    g_topk_idx[TRX];
__device__ float  g_topk_w[TRX];
__device__ int    g_counts[E_EXP];
__device__ int    g_cursor[E_EXP];
__device__ float  g_probs_sum[E_EXP];
__device__ float  g_z2_sum;
__device__ int    g_perm_src[TRX];
__device__ float  g_wsort[TRX];
__device__ int    g_tile_e[MAXT];
__device__ int    g_tile_row[MAXT];
__device__ int    g_tile_nrows[MAXT];
__device__ int    g_ntiles;
__device__ __half g_gated[(size_t)TRX * I_DIM];
__device__ __half g_w1h[(size_t)E_EXP * D_DIM * I_DIM];
__device__ __half g_w2h[(size_t)E_EXP * D_DIM * I_DIM];
__device__ __half g_w3h[(size_t)E_EXP * I_DIM * D_DIM];
__device__ __half g_xh[(size_t)T_TOK * D_DIM];

__device__ __forceinline__ uint32_t smem_u32(const void* p) {
  return (uint32_t)__cvta_generic_to_shared(p);
}
#define CP_ASYNC16(dst_u32, src_ptr) \
  asm volatile("cp.async.cg.shared.global [%0], [%1], 16;\n" :: "r"(dst_u32), "l"(src_ptr))
#define CP_COMMIT() asm volatile("cp.async.commit_group;\n" ::)
#define CP_WAIT(N)  asm volatile("cp.async.wait_group %0;\n" :: "n"(N))

__device__ __forceinline__ void mma16816(float* c, const uint32_t* a, const uint32_t* b) {
  asm volatile(
    "mma.sync.aligned.m16n8k16.row.col.f32.f16.f16.f32 "
    "{%0,%1,%2,%3}, {%4,%5,%6,%7}, {%8,%9}, {%0,%1,%2,%3};\n"
    : "+f"(c[0]), "+f"(c[1]), "+f"(c[2]), "+f"(c[3])
    : "r"(a[0]), "r"(a[1]), "r"(a[2]), "r"(a[3]), "r"(b[0]), "r"(b[1]));
}
#define LDSM_X4(a, addr) \
  asm volatile("ldmatrix.sync.aligned.m8n8.x4.shared.b16 {%0,%1,%2,%3}, [%4];" \
    : "=r"((a)[0]), "=r"((a)[1]), "=r"((a)[2]), "=r"((a)[3]) : "r"(addr))
#define LDSM_X4T(b, addr) \
  asm volatile("ldmatrix.sync.aligned.m8n8.x4.trans.shared.b16 {%0,%1,%2,%3}, [%4];" \
    : "=r"((b)[0]), "=r"((b)[1]), "=r"((b)[2]), "=r"((b)[3]) : "r"(addr))
#define REDADD(ptr, val) \
  asm volatile("red.global.add.f32 [%0], %1;" :: "l"(ptr), "f"(val) : "memory")

// ------------------------------- conversion -------------------------------
#define WN (E_EXP * D_DIM * I_DIM)     // 25165824
#define WBLK16 (WN / 4096)             // 6144 blocks per weight (16 floats/thread)

__global__ void cvt_w_kernel(const float* __restrict__ src, int which) {
  __half* dst = (which == 0) ? g_w1h : (which == 1) ? g_w2h : g_w3h;
  size_t i = ((size_t)blockIdx.x * 256 + threadIdx.x) * 16;
  float4 f0 = *(const float4*)(src + i);
  float4 f1 = *(const float4*)(src + i + 4);
  float4 f2 = *(const float4*)(src + i + 8);
  float4 f3 = *(const float4*)(src + i + 12);
  __align__(16) __half2 h[8];
  h[0] = __floats2half2_rn(f0.x, f0.y);
  h[1] = __floats2half2_rn(f0.z, f0.w);
  h[2] = __floats2half2_rn(f1.x, f1.y);
  h[3] = __floats2half2_rn(f1.z, f1.w);
  h[4] = __floats2half2_rn(f2.x, f2.y);
  h[5] = __floats2half2_rn(f2.z, f2.w);
  h[6] = __floats2half2_rn(f3.x, f3.y);
  h[7] = __floats2half2_rn(f3.z, f3.w);
  *(uint4*)(dst + i)     = *(uint4*)h;
  *(uint4*)(dst + i + 8) = *(uint4*)(h + 4);
}

// ------------------------------- small kernels --------------------------------
__global__ void zero_kernel() {
  int t = threadIdx.x;
  if (t < E_EXP) { g_counts[t] = 0; g_cursor[t] = 0; g_probs_sum[t] = 0.f; }
  if (t == 0) { g_z2_sum = 0.f; g_ntiles = 0; }
}

__global__ void zero_out_kernel(float* __restrict__ out) {
  size_t i = ((size_t)blockIdx.x * 256 + threadIdx.x) * 4;
  *(float4*)(out + i) = make_float4(0.f, 0.f, 0.f, 0.f);
}

// router: vectorized; also emits fp16 x mirror
__global__ void router_kernel(const float* __restrict__ x, const float* __restrict__ rw) {
  int warp = threadIdx.x >> 5;
  int lane = threadIdx.x & 31;
  int token = blockIdx.x * 8 + warp;
  const float4* xr4 = (const float4*)(x + (size_t)token * D_DIM);
  __half* xhr = g_xh + (size_t)token * D_DIM;
  float acc[E_EXP];
#pragma unroll
  for (int e = 0; e < E_EXP; e++) acc[e] = 0.f;
#pragma unroll 2
  for (int i = lane; i < D_DIM / 4; i += 32) {
    float4 xv = xr4[i];
    __align__(8) __half2 hh[2];
    hh[0] = __floats2half2_rn(xv.x, xv.y);
    hh[1] = __floats2half2_rn(xv.z, xv.w);
    *(uint2*)(xhr + i * 4) = *(uint2*)hh;
    const float4* w4 = (const float4*)(rw + (size_t)i * 4 * E_EXP);
    float xs[4] = {xv.x, xv.y, xv.z, xv.w};
#pragma unroll
    for (int r = 0; r < 4; r++) {
      float4 wa = w4[r * 2], wb = w4[r * 2 + 1];
      acc[0] += xs[r] * wa.x; acc[1] += xs[r] * wa.y;
      acc[2] += xs[r] * wa.z; acc[3] += xs[r] * wa.w;
      acc[4] += xs[r] * wb.x; acc[5] += xs[r] * wb.y;
      acc[6] += xs[r] * wb.z; acc[7] += xs[r] * wb.w;
    }
  }
#pragma unroll
  for (int e = 0; e < E_EXP; e++) {
#pragma unroll
    for (int o = 16; o > 0; o >>= 1) acc[e] += __shfl_xor_sync(0xffffffffu, acc[e], o);
  }
  if (lane == 0) {
    float m = acc[0];
#pragma unroll
    for (int e = 1; e < E_EXP; e++) m = fmaxf(m, acc[e]);
    float p[E_EXP]; float se = 0.f;
#pragma unroll
    for (int e = 0; e < E_EXP; e++) { p[e] = expf(acc[e] - m); se += p[e]; }
    float inv = 1.f / se;
#pragma unroll
    for (int e = 0; e < E_EXP; e++) p[e] *= inv;
    float z = m + logf(se);
    atomicAdd(&g_z2_sum, z * z);
#pragma unroll
    for (int e = 0; e < E_EXP; e++) atomicAdd(&g_probs_sum[e], p[e]);
    int i0 = 0;
#pragma unroll
    for (int e = 1; e < E_EXP; e++) if (acc[e] > acc[i0]) i0 = e;
    int i1 = (i0 == 0) ? 1 : 0;
#pragma unroll
    for (int e = 0; e < E_EXP; e++) if (e != i0 && acc[e] > acc[i1]) i1 = e;
    float s = p[i0] + p[i1];
    g_topk_idx[token * 2 + 0] = i0;
    g_topk_idx[token * 2 + 1] = i1;
    g_topk_w[token * 2 + 0] = p[i0] / s;
    g_topk_w[token * 2 + 1] = p[i1] / s;
    atomicAdd(&g_counts[i0], 1);
    atomicAdd(&g_counts[i1], 1);
  }
}

__global__ void scan_kernel() {
  if (threadIdx.x == 0) {
    int off = 0, nt = 0;
    for (int e = 0; e < E_EXP; e++) {
      g_cursor[e] = off;
      int c = g_counts[e];
      for (int r = 0; r < c; r += BM) {
        g_tile_e[nt] = e;
        g_tile_row[nt] = off + r;
        g_tile_nrows[nt] = (c - r < BM) ? (c - r) : BM;
        nt++;
      }
      off += c;
    }
    g_ntiles = nt;
  }
}

__global__ void scatter_kernel() {
  int i = blockIdx.x * 256 + threadIdx.x;
  if (i < TRX) {
    int e = g_topk_idx[i];
    int pos = atomicAdd(&g_cursor[e], 1);
    g_perm_src[pos] = i >> 1;
    g_wsort[pos] = g_topk_w[i];
  }
}

// ------------------- smem layout (BK=64) -------------------
#define A_ST 18432
#define B1_ST 9216
#define G1_A  1024
#define G1_B1 (G1_A + STAGES * A_ST)       // 56320
#define G1_B2 (G1_B1 + STAGES * B1_ST)     // 83968
#define G1_SMEM (G1_B2 + STAGES * B1_ST)   // 111616
#define B2_ST 17408
#define G2_A 0
#define G2_B (STAGES * A_ST)               // 55296
#define G2_SMEM (G2_B + STAGES * B2_ST)    // 107520

// ------------------- GEMM1: gated = silu(Xg*W1) * (Xg*W2) -------------------
__global__ __launch_bounds__(256, 2)
void gemm1_kernel() {
  int tile = blockIdx.y;
  if (tile >= g_ntiles) return;
  extern __shared__ char sm[];
  const int tid = threadIdx.x;
  const int e = g_tile_e[tile];
  const int row0 = g_tile_row[tile];
  const int nrows = g_tile_nrows[tile];
  const int n0 = blockIdx.x * 64;
  const __half* __restrict__ W1 = g_w1h + (size_t)e * D_DIM * I_DIM;
  const __half* __restrict__ W2 = g_w2h + (size_t)e * D_DIM * I_DIM;

  int* rowtok = (int*)sm;
  if (tid < BM) {
    int r = row0 + tid;
    rowtok[tid] = g_perm_src[r < TRX ? r : TRX - 1];
  }
  __syncthreads();

  const __half* ap[4];
  uint32_t ad[4];
#pragma unroll
  for (int q = 0; q < 4; q++) {
    int id = tid + q * 256;
    int r = id >> 3, cc = (id & 7) << 3;
    ap[q] = g_xh + (size_t)rowtok[r] * D_DIM + cc;
    ad[q] = smem_u32(sm + G1_A) + (r * 72 + cc) * 2;
  }
  const __half* b1p[2]; const __half* b2p[2];
  uint32_t b1d[2], b2d[2];
#pragma unroll
  for (int q = 0; q < 2; q++) {
    int id = tid + q * 256;
    int r = id >> 3, cc = (id & 7) << 3;
    b1p[q] = W1 + (size_t)r * I_DIM + n0 + cc;
    b2p[q] = W2 + (size_t)r * I_DIM + n0 + cc;
    b1d[q] = smem_u32(sm + G1_B1) + (r * 72 + cc) * 2;
    b2d[q] = smem_u32(sm + G1_B2) + (r * 72 + cc) * 2;
  }

  float c1[2][4][4], c2[2][4][4];
#pragma unroll
  for (int i = 0; i < 2; i++)
#pragma unroll
    for (int j = 0; j < 4; j++)
#pragma unroll
      for (int q = 0; q < 4; q++) { c1[i][j][q] = 0.f; c2[i][j][q] = 0.f; }

  const int lane = tid & 31;
  const int wid = tid >> 5;
  const int wm = wid >> 1;
  const int wn = wid & 1;
  const int btr = (lane & 7) + ((lane >> 3) & 1) * 8;
  const int btc = wn * 32 + ((lane >> 4) << 3);
  const int atr = wm * 32 + (lane & 15);
  const int atc = (lane >> 4) << 3;

  const int NK = D_DIM / BK;  // 16
#pragma unroll
  for (int s = 0; s < STAGES - 1; s++) {
    int k0 = s * BK;
#pragma unroll
    for (int q = 0; q < 4; q++) CP_ASYNC16(ad[q] + s * A_ST, ap[q] + k0);
#pragma unroll
    for (int q = 0; q < 2; q++) {
      CP_ASYNC16(b1d[q] + s * B1_ST, b1p[q] + (size_t)k0 * I_DIM);
      CP_ASYNC16(b2d[q] + s * B1_ST, b2p[q] + (size_t)k0 * I_DIM);
    }
    CP_COMMIT();
  }

#pragma unroll 1
  for (int it = 0; it < NK; it++) {
    const int buf = it % STAGES;
    CP_WAIT(STAGES - 2);
    __syncthreads();
    {
      int pf = it + STAGES - 1;
      if (pf < NK) {
        int sb = pf % STAGES;
        int k0 = pf * BK;
#pragma unroll
        for (int q = 0; q < 4; q++) CP_ASYNC16(ad[q] + sb * A_ST, ap[q] + k0);
#pragma unroll
        for (int q = 0; q < 2; q++) {
          CP_ASYNC16(b1d[q] + sb * B1_ST, b1p[q] + (size_t)k0 * I_DIM);
          CP_ASYNC16(b2d[q] + sb * B1_ST, b2p[q] + (size_t)k0 * I_DIM);
        }
      }
      CP_COMMIT();
    }
    const __half* As  = (const __half*)(sm + G1_A  + buf * A_ST);
    const __half* B1s = (const __half*)(sm + G1_B1 + buf * B1_ST);
    const __half* B2s = (const __half*)(sm + G1_B2 + buf * B1_ST);

#pragma unroll
    for (int kk = 0; kk < BK; kk += 16) {
      uint32_t a[2][4];
#pragma unroll
      for (int mf = 0; mf < 2; mf++) {
        uint32_t aad = smem_u32(As + (size_t)(atr + mf * 16) * 72 + kk + atc);
        LDSM_X4(a[mf], aad);
      }
#pragma unroll
      for (int nh = 0; nh < 2; nh++) {
        uint32_t b[4];
        uint32_t bad1 = smem_u32(B1s + (size_t)(kk + btr) * 72 + btc + nh * 16);
        LDSM_X4T(b, bad1);
        mma16816(c1[0][nh * 2],     a[0], b);
        mma16816(c1[0][nh * 2 + 1], a[0], b + 2);
        mma16816(c1[1][nh * 2],     a[1], b);
        mma16816(c1[1][nh * 2 + 1], a[1], b + 2);
        uint32_t bad2 = smem_u32(B2s + (size_t)(kk + btr) * 72 + btc + nh * 16);
        LDSM_X4T(b, bad2);
        mma16816(c2[0][nh * 2],     a[0], b);
        mma16816(c2[0][nh * 2 + 1], a[0], b + 2);
        mma16816(c2[1][nh * 2],     a[1], b);
        mma16816(c2[1][nh * 2 + 1], a[1], b + 2);
      }
    }
  }

  const int grp = lane >> 2;
  const int qp  = (lane & 3) << 1;
#pragma unroll
  for (int mf = 0; mf < 2; mf++) {
#pragma unroll
    for (int nf = 0; nf < 4; nf++) {
#pragma unroll
      for (int h8 = 0; h8 < 2; h8++) {
        int rl = wm * 32 + mf * 16 + grp + h8 * 8;
        if (rl < nrows) {
          float h1a = c1[mf][nf][h8 * 2 + 0];
          float h1b = c1[mf][nf][h8 * 2 + 1];
          float h2a = c2[mf][nf][h8 * 2 + 0];
          float h2b = c2[mf][nf][h8 * 2 + 1];
          float ga = (h1a / (1.f + __expf(-h1a))) * h2a;
          float gb = (h1b / (1.f + __expf(-h1b))) * h2b;
          size_t o = (size_t)(row0 + rl) * I_DIM + (n0 + wn * 32 + nf * 8 + qp);
          *(__half2*)&g_gated[o] = __floats2half2_rn(ga, gb);
        }
      }
    }
  }
}

// ------------------- GEMM2: out += w * (gated * W3)  (fused combine) -------------------
__global__ __launch_bounds__(256, 2)
void gemm2_kernel(float* __restrict__ out) {
  int tile = blockIdx.y;
  if (tile >= g_ntiles) return;
  extern __shared__ char sm[];
  __shared__ int   tok_s[BM];
  __shared__ float w_s[BM];
  const int tid = threadIdx.x;
  const int e = g_tile_e[tile];
  const int row0 = g_tile_row[tile];
  const int nrows = g_tile_nrows[tile];
  const int n0 = blockIdx.x * 128;
  const __half* __restrict__ W3 = g_w3h + (size_t)e * I_DIM * D_DIM;

  if (tid < BM) {
    int r = row0 + tid;
    int rc = r < TRX ? r : TRX - 1;
    tok_s[tid] = g_perm_src[rc];
    w_s[tid] = g_wsort[rc];
  }

  const __half* ap[4];
  uint32_t ad[4];
#pragma unroll
  for (int q = 0; q < 4; q++) {
    int id = tid + q * 256;
    int r = id >> 3, cc = (id & 7) << 3;
    int srcr = row0 + r; if (srcr >= TRX) srcr = TRX - 1;
    ap[q] = g_gated + (size_t)srcr * I_DIM + cc;
    ad[q] = smem_u32(sm + G2_A) + (r * 72 + cc) * 2;
  }
  const __half* bp[4];
  uint32_t bd[4];
#pragma unroll
  for (int q = 0; q < 4; q++) {
    int id = tid + q * 256;
    int r = id >> 4, cc = (id & 15) << 3;
    bp[q] = W3 + (size_t)r * D_DIM + n0 + cc;
    bd[q] = smem_u32(sm + G2_B) + (r * 136 + cc) * 2;
  }

  float c[4][4][4];
#pragma unroll
  for (int i = 0; i < 4; i++)
#pragma unroll
    for (int j = 0; j < 4; j++)
#pragma unroll
      for (int q = 0; q < 4; q++) c[i][j][q] = 0.f;

  const int lane = tid & 31;
  const int wid = tid >> 5;
  const int wm = wid >> 2;
  const int wn = wid & 3;
  const int btr = (lane & 7) + ((lane >> 3) & 1) * 8;
  const int btc = wn * 32 + ((lane >> 4) << 3);
  const int atr = wm * 64 + (lane & 15);
  const int atc = (lane >> 4) << 3;

  const int NK = I_DIM / BK;  // 48
#pragma unroll
  for (int s = 0; s < STAGES - 1; s++) {
    int k0 = s * BK;
#pragma unroll
    for (int q = 0; q < 4; q++) CP_ASYNC16(ad[q] + s * A_ST, ap[q] + k0);
#pragma unroll
    for (int q = 0; q < 4; q++) CP_ASYNC16(bd[q] + s * B2_ST, bp[q] + (size_t)k0 * D_DIM);
    CP_COMMIT();
  }

#pragma unroll 1
  for (int it = 0; it < NK; it++) {
    const int buf = it % STAGES;
    CP_WAIT(STAGES - 2);
    __syncthreads();
    {
      int pf = it + STAGES - 1;
      if (pf < NK) {
        int sb = pf % STAGES;
        int k0 = pf * BK;
#pragma unroll
        for (int q = 0; q < 4; q++) CP_ASYNC16(ad[q] + sb * A_ST, ap[q] + k0);
#pragma unroll
        for (int q = 0; q < 4; q++) CP_ASYNC16(bd[q] + sb * B2_ST, bp[q] + (size_t)k0 * D_DIM);
      }
      CP_COMMIT();
    }
    const __half* As = (const __half*)(sm + G2_A + buf * A_ST);
    const __half* Bs = (const __half*)(sm + G2_B + buf * B2_ST);

#pragma unroll
    for (int kk = 0; kk < BK; kk += 16) {
      uint32_t a[4][4];
#pragma unroll
      for (int mf = 0; mf < 4; mf++) {
        uint32_t aad = smem_u32(As + (size_t)(atr + mf * 16) * 72 + kk + atc);
        LDSM_X4(a[mf], aad);
      }
#pragma unroll
      for (int nh = 0; nh < 2; nh++) {
        uint32_t b[4];
        uint32_t bad = smem_u32(Bs + (size_t)(kk + btr) * 136 + btc + nh * 16);
        LDSM_X4T(b, bad);
#pragma unroll
        for (int mf = 0; mf < 4; mf++) {
          mma16816(c[mf][nh * 2],     a[mf], b);
          mma16816(c[mf][nh * 2 + 1], a[mf], b + 2);
        }
      }
    }
  }

  const int grp = lane >> 2;
  const int qp  = (lane & 3) << 1;
#pragma unroll
  for (int mf = 0; mf < 4; mf++) {
#pragma unroll
    for (int h8 = 0; h8 < 2; h8++) {
      int rl = wm * 64 + mf * 16 + grp + h8 * 8;
      if (rl < nrows) {
        float w = w_s[rl];
        float* orow = out + (size_t)tok_s[rl] * D_DIM + n0 + wn * 32 + qp;
#pragma unroll
        for (int nf = 0; nf < 4; nf++) {
          REDADD(orow + nf * 8,     w * c[mf][nf][h8 * 2 + 0]);
          REDADD(orow + nf * 8 + 1, w * c[mf][nf][h8 * 2 + 1]);
        }
      }
    }
  }
}

// ------------------- aux -------------------
__global__ void aux_kernel(float* __restrict__ aux) {
  int t = threadIdx.x;
  if (t < E_EXP) aux[t] = (float)g_counts[t] / (float)TRX;
  if (t == 0) {
    float lbl = 0.f;
    for (int e = 0; e < E_EXP; e++) {
      float f = ((float)g_counts[e] / (float)TRX) * ((float)E_EXP / 2.f);
      float pm = g_probs_sum[e] / (float)T_TOK;
      lbl += f * pm;
    }
    aux[E_EXP]     = 0.01f  * lbl;
    aux[E_EXP + 1] = 0.001f * (g_z2_sum / (float)T_TOK);
  }
}

// ------------------------------- launch -------------------------------
extern "C" void kernel_launch(void* const* d_in, const int* in_sizes, int n_in,
                              void* d_out, int out_size) {
  const float* x  = (const float*)d_in[0];
  const float* rw = (const float*)d_in[1];
  const float* w1 = (const float*)d_in[2];
  const float* w2 = (const float*)d_in[3];
  const float* w3 = (const float*)d_in[4];
  float* out = (float*)d_out;

  static cudaStream_t s2 = nullptr;
  static cudaEvent_t ev_fork = nullptr, ev_cvt12 = nullptr, ev_cvt3 = nullptr;
  if (s2 == nullptr) {
    cudaStreamCreateWithFlags(&s2, cudaStreamNonBlocking);
    cudaEventCreateWithFlags(&ev_fork,  cudaEventDisableTiming);
    cudaEventCreateWithFlags(&ev_cvt12, cudaEventDisableTiming);
    cudaEventCreateWithFlags(&ev_cvt3,  cudaEventDisableTiming);
    cudaFuncSetAttribute(gemm1_kernel, cudaFuncAttributeMaxDynamicSharedMemorySize, G1_SMEM);
    cudaFuncSetAttribute(gemm2_kernel, cudaFuncAttributeMaxDynamicSharedMemorySize, G2_SMEM);
  }

  // fork: out-zero + weight conversion on side stream; token pipeline on main
  cudaEventRecord(ev_fork, 0);
  cudaStreamWaitEvent(s2, ev_fork, 0);
  zero_out_kernel<<<T_TOK * D_DIM / 1024, 256, 0, s2>>>(out);
  cvt_w_kernel<<<WBLK16, 256, 0, s2>>>(w1, 0);
  cvt_w_kernel<<<WBLK16, 256, 0, s2>>>(w2, 1);
  cudaEventRecord(ev_cvt12, s2);
  cvt_w_kernel<<<WBLK16, 256, 0, s2>>>(w3, 2);
  cudaEventRecord(ev_cvt3, s2);                      // orders zero_out + cvt3

  zero_kernel<<<1, 32>>>();
  router_kernel<<<T_TOK / 8, 256>>>(x, rw);          // also writes g_xh
  aux_kernel<<<1, 32>>>(out + (size_t)T_TOK * D_DIM); // counts/probs/z2 final here
  scan_kernel<<<1, 1>>>();
  scatter_kernel<<<TRX / 256, 256>>>();

  cudaStreamWaitEvent(0, ev_cvt12, 0);               // need w1h/w2h
  gemm1_kernel<<<dim3(I_DIM / 64, GRID_TILES), 256, G1_SMEM>>>();
  cudaStreamWaitEvent(0, ev_cvt3, 0);                // need w3h + zeroed out
  gemm2_kernel<<<dim3(D_DIM / 128, GRID_TILES), 256, G2_SMEM>>>(out);
}

// round 15
// speedup vs baseline: 1.0081x; 1.0081x over previous
#include <cuda_runtime.h>
#include <cuda_fp16.h>
#include <cstdint>

#define T_TOK 8192
#define D_DIM 1024
#define E_EXP 8
#define I_DIM 3072
#define TRX   16384
#define BM 128
#define BK 64
#define STAGES 3
#define MAXT 144
#define GRID_TILES 136   // max sum ceil(count_e/128)

// ------------------- device scratch (static: no allocation) -------------------
__device__ int    g_topk_idx[TRX];
__device__ float  g_topk_w[TRX];
__device__ int    g_counts[E_EXP];
__device__ int    g_cursor[E_EXP];
__device__ float  g_probs_sum[E_EXP];
__device__ float  g_z2_sum;
__device__ int    g_perm_src[TRX];
__device__ float  g_wsort[TRX];
__device__ int    g_tile_e[MAXT];
__device__ int    g_tile_row[MAXT];
__device__ int    g_tile_nrows[MAXT];
__device__ int    g_ntiles;
__device__ __half g_gated[(size_t)TRX * I_DIM];
__device__ __half g_w1h[(size_t)E_EXP * D_DIM * I_DIM];
__device__ __half g_w2h[(size_t)E_EXP * D_DIM * I_DIM];
__device__ __half g_w3h[(size_t)E_EXP * I_DIM * D_DIM];
__device__ __half g_xh[(size_t)T_TOK * D_DIM];

__device__ __forceinline__ uint32_t smem_u32(const void* p) {
  return (uint32_t)__cvta_generic_to_shared(p);
}
#define CP_ASYNC16(dst_u32, src_ptr) \
  asm volatile("cp.async.cg.shared.global [%0], [%1], 16;\n" :: "r"(dst_u32), "l"(src_ptr))
#define CP_COMMIT() asm volatile("cp.async.commit_group;\n" ::)
#define CP_WAIT(N)  asm volatile("cp.async.wait_group %0;\n" :: "n"(N))

__device__ __forceinline__ void mma16816(float* c, const uint32_t* a, const uint32_t* b) {
  asm volatile(
    "mma.sync.aligned.m16n8k16.row.col.f32.f16.f16.f32 "
    "{%0,%1,%2,%3}, {%4,%5,%6,%7}, {%8,%9}, {%0,%1,%2,%3};\n"
    : "+f"(c[0]), "+f"(c[1]), "+f"(c[2]), "+f"(c[3])
    : "r"(a[0]), "r"(a[1]), "r"(a[2]), "r"(a[3]), "r"(b[0]), "r"(b[1]));
}
#define LDSM_X4(a, addr) \
  asm volatile("ldmatrix.sync.aligned.m8n8.x4.shared.b16 {%0,%1,%2,%3}, [%4];" \
    : "=r"((a)[0]), "=r"((a)[1]), "=r"((a)[2]), "=r"((a)[3]) : "r"(addr))
#define LDSM_X4T(b, addr) \
  asm volatile("ldmatrix.sync.aligned.m8n8.x4.trans.shared.b16 {%0,%1,%2,%3}, [%4];" \
    : "=r"((b)[0]), "=r"((b)[1]), "=r"((b)[2]), "=r"((b)[3]) : "r"(addr))
#define REDADD(ptr, val) \
  asm volatile("red.global.add.f32 [%0], %1;" :: "l"(ptr), "f"(val) : "memory")

// ------------------------------- conversion -------------------------------
#define WN (E_EXP * D_DIM * I_DIM)     // 25165824
#define WBLK16 (WN / 4096)             // 6144 blocks per weight (16 floats/thread)

__global__ void cvt_w_kernel(const float* __restrict__ src, int which) {
  __half* dst = (which == 0) ? g_w1h : (which == 1) ? g_w2h : g_w3h;
  size_t i = ((size_t)blockIdx.x * 256 + threadIdx.x) * 16;
  float4 f0 = *(const float4*)(src + i);
  float4 f1 = *(const float4*)(src + i + 4);
  float4 f2 = *(const float4*)(src + i + 8);
  float4 f3 = *(const float4*)(src + i + 12);
  __align__(16) __half2 h[8];
  h[0] = __floats2half2_rn(f0.x, f0.y);
  h[1] = __floats2half2_rn(f0.z, f0.w);
  h[2] = __floats2half2_rn(f1.x, f1.y);
  h[3] = __floats2half2_rn(f1.z, f1.w);
  h[4] = __floats2half2_rn(f2.x, f2.y);
  h[5] = __floats2half2_rn(f2.z, f2.w);
  h[6] = __floats2half2_rn(f3.x, f3.y);
  h[7] = __floats2half2_rn(f3.z, f3.w);
  *(uint4*)(dst + i)     = *(uint4*)h;
  *(uint4*)(dst + i + 8) = *(uint4*)(h + 4);
}

// ------------------------------- small kernels --------------------------------
__global__ void zero_kernel() {
  int t = threadIdx.x;
  if (t < E_EXP) { g_counts[t] = 0; g_cursor[t] = 0; g_probs_sum[t] = 0.f; }
  if (t == 0) { g_z2_sum = 0.f; g_ntiles = 0; }
}

__global__ void zero_out_kernel(float* __restrict__ out) {
  size_t i = ((size_t)blockIdx.x * 256 + threadIdx.x) * 4;
  *(float4*)(out + i) = make_float4(0.f, 0.f, 0.f, 0.f);
}

// router: vectorized; also emits fp16 x mirror
__global__ void router_kernel(const float* __restrict__ x, const float* __restrict__ rw) {
  int warp = threadIdx.x >> 5;
  int lane = threadIdx.x & 31;
  int token = blockIdx.x * 8 + warp;
  const float4* xr4 = (const float4*)(x + (size_t)token * D_DIM);
  __half* xhr = g_xh + (size_t)token * D_DIM;
  float acc[E_EXP];
#pragma unroll
  for (int e = 0; e < E_EXP; e++) acc[e] = 0.f;
#pragma unroll 2
  for (int i = lane; i < D_DIM / 4; i += 32) {
    float4 xv = xr4[i];
    __align__(8) __half2 hh[2];
    hh[0] = __floats2half2_rn(xv.x, xv.y);
    hh[1] = __floats2half2_rn(xv.z, xv.w);
    *(uint2*)(xhr + i * 4) = *(uint2*)hh;
    const float4* w4 = (const float4*)(rw + (size_t)i * 4 * E_EXP);
    float xs[4] = {xv.x, xv.y, xv.z, xv.w};
#pragma unroll
    for (int r = 0; r < 4; r++) {
      float4 wa = w4[r * 2], wb = w4[r * 2 + 1];
      acc[0] += xs[r] * wa.x; acc[1] += xs[r] * wa.y;
      acc[2] += xs[r] * wa.z; acc[3] += xs[r] * wa.w;
      acc[4] += xs[r] * wb.x; acc[5] += xs[r] * wb.y;
      acc[6] += xs[r] * wb.z; acc[7] += xs[r] * wb.w;
    }
  }
#pragma unroll
  for (int e = 0; e < E_EXP; e++) {
#pragma unroll
    for (int o = 16; o > 0; o >>= 1) acc[e] += __shfl_xor_sync(0xffffffffu, acc[e], o);
  }
  if (lane == 0) {
    float m = acc[0];
#pragma unroll
    for (int e = 1; e < E_EXP; e++) m = fmaxf(m, acc[e]);
    float p[E_EXP]; float se = 0.f;
#pragma unroll
    for (int e = 0; e < E_EXP; e++) { p[e] = expf(acc[e] - m); se += p[e]; }
    float inv = 1.f / se;
#pragma unroll
    for (int e = 0; e < E_EXP; e++) p[e] *= inv;
    float z = m + logf(se);
    atomicAdd(&g_z2_sum, z * z);
#pragma unroll
    for (int e = 0; e < E_EXP; e++) atomicAdd(&g_probs_sum[e], p[e]);
    int i0 = 0;
#pragma unroll
    for (int e = 1; e < E_EXP; e++) if (acc[e] > acc[i0]) i0 = e;
    int i1 = (i0 == 0) ? 1 : 0;
#pragma unroll
    for (int e = 0; e < E_EXP; e++) if (e != i0 && acc[e] > acc[i1]) i1 = e;
    float s = p[i0] + p[i1];
    g_topk_idx[token * 2 + 0] = i0;
    g_topk_idx[token * 2 + 1] = i1;
    g_topk_w[token * 2 + 0] = p[i0] / s;
    g_topk_w[token * 2 + 1] = p[i1] / s;
    atomicAdd(&g_counts[i0], 1);
    atomicAdd(&g_counts[i1], 1);
  }
}

// scan + aux fused (both depend only on router results; single block)
__global__ void scan_aux_kernel(float* __restrict__ aux) {
  int t = threadIdx.x;
  if (t < E_EXP) aux[t] = (float)g_counts[t] / (float)TRX;
  if (t == 0) {
    float lbl = 0.f;
    int off = 0, nt = 0;
    for (int e = 0; e < E_EXP; e++) {
      g_cursor[e] = off;
      int c = g_counts[e];
      float f = ((float)c / (float)TRX) * ((float)E_EXP / 2.f);
      float pm = g_probs_sum[e] / (float)T_TOK;
      lbl += f * pm;
      for (int r = 0; r < c; r += BM) {
        g_tile_e[nt] = e;
        g_tile_row[nt] = off + r;
        g_tile_nrows[nt] = (c - r < BM) ? (c - r) : BM;
        nt++;
      }
      off += c;
    }
    g_ntiles = nt;
    aux[E_EXP]     = 0.01f  * lbl;
    aux[E_EXP + 1] = 0.001f * (g_z2_sum / (float)T_TOK);
  }
}

__global__ void scatter_kernel() {
  int i = blockIdx.x * 256 + threadIdx.x;
  if (i < TRX) {
    int e = g_topk_idx[i];
    int pos = atomicAdd(&g_cursor[e], 1);
    g_perm_src[pos] = i >> 1;
    g_wsort[pos] = g_topk_w[i];
  }
}

// ------------------- smem layout (BK=64) -------------------
#define A_ST 18432
#define B1_ST 9216
#define G1_A  1024
#define G1_B1 (G1_A + STAGES * A_ST)       // 56320
#define G1_B2 (G1_B1 + STAGES * B1_ST)     // 83968
#define G1_SMEM (G1_B2 + STAGES * B1_ST)   // 111616
#define B2_ST 17408
#define G2_A 0
#define G2_B (STAGES * A_ST)               // 55296
#define G2_SMEM (G2_B + STAGES * B2_ST)    // 107520

// ------------------- GEMM1: gated = silu(Xg*W1) * (Xg*W2) -------------------
__global__ __launch_bounds__(256, 2)
void gemm1_kernel() {
  int tile = blockIdx.y;
  if (tile >= g_ntiles) return;
  extern __shared__ char sm[];
  const int tid = threadIdx.x;
  const int e = g_tile_e[tile];
  const int row0 = g_tile_row[tile];
  const int nrows = g_tile_nrows[tile];
  const int n0 = blockIdx.x * 64;
  const __half* __restrict__ W1 = g_w1h + (size_t)e * D_DIM * I_DIM;
  const __half* __restrict__ W2 = g_w2h + (size_t)e * D_DIM * I_DIM;

  int* rowtok = (int*)sm;
  if (tid < BM) {
    int r = row0 + tid;
    rowtok[tid] = g_perm_src[r < TRX ? r : TRX - 1];
  }
  __syncthreads();

  const __half* ap[4];
  uint32_t ad[4];
#pragma unroll
  for (int q = 0; q < 4; q++) {
    int id = tid + q * 256;
    int r = id >> 3, cc = (id & 7) << 3;
    ap[q] = g_xh + (size_t)rowtok[r] * D_DIM + cc;
    ad[q] = smem_u32(sm + G1_A) + (r * 72 + cc) * 2;
  }
  const __half* b1p[2]; const __half* b2p[2];
  uint32_t b1d[2], b2d[2];
#pragma unroll
  for (int q = 0; q < 2; q++) {
    int id = tid + q * 256;
    int r = id >> 3, cc = (id & 7) << 3;
    b1p[q] = W1 + (size_t)r * I_DIM + n0 + cc;
    b2p[q] = W2 + (size_t)r * I_DIM + n0 + cc;
    b1d[q] = smem_u32(sm + G1_B1) + (r * 72 + cc) * 2;
    b2d[q] = smem_u32(sm + G1_B2) + (r * 72 + cc) * 2;
  }

  float c1[2][4][4], c2[2][4][4];
#pragma unroll
  for (int i = 0; i < 2; i++)
#pragma unroll
    for (int j = 0; j < 4; j++)
#pragma unroll
      for (int q = 0; q < 4; q++) { c1[i][j][q] = 0.f; c2[i][j][q] = 0.f; }

  const int lane = tid & 31;
  const int wid = tid >> 5;
  const int wm = wid >> 1;
  const int wn = wid & 1;
  const int btr = (lane & 7) + ((lane >> 3) & 1) * 8;
  const int btc = wn * 32 + ((lane >> 4) << 3);
  const int atr = wm * 32 + (lane & 15);
  const int atc = (lane >> 4) << 3;

  const int NK = D_DIM / BK;  // 16
#pragma unroll
  for (int s = 0; s < STAGES - 1; s++) {
    int k0 = s * BK;
#pragma unroll
    for (int q = 0; q < 4; q++) CP_ASYNC16(ad[q] + s * A_ST, ap[q] + k0);
#pragma unroll
    for (int q = 0; q < 2; q++) {
      CP_ASYNC16(b1d[q] + s * B1_ST, b1p[q] + (size_t)k0 * I_DIM);
      CP_ASYNC16(b2d[q] + s * B1_ST, b2p[q] + (size_t)k0 * I_DIM);
    }
    CP_COMMIT();
  }

#pragma unroll 1
  for (int it = 0; it < NK; it++) {
    const int buf = it % STAGES;
    CP_WAIT(STAGES - 2);
    __syncthreads();
    {
      int pf = it + STAGES - 1;
      if (pf < NK) {
        int sb = pf % STAGES;
        int k0 = pf * BK;
#pragma unroll
        for (int q = 0; q < 4; q++) CP_ASYNC16(ad[q] + sb * A_ST, ap[q] + k0);
#pragma unroll
        for (int q = 0; q < 2; q++) {
          CP_ASYNC16(b1d[q] + sb * B1_ST, b1p[q] + (size_t)k0 * I_DIM);
          CP_ASYNC16(b2d[q] + sb * B1_ST, b2p[q] + (size_t)k0 * I_DIM);
        }
      }
      CP_COMMIT();
    }
    const __half* As  = (const __half*)(sm + G1_A  + buf * A_ST);
    const __half* B1s = (const __half*)(sm + G1_B1 + buf * B1_ST);
    const __half* B2s = (const __half*)(sm + G1_B2 + buf * B1_ST);

#pragma unroll
    for (int kk = 0; kk < BK; kk += 16) {
      uint32_t a[2][4];
#pragma unroll
      for (int mf = 0; mf < 2; mf++) {
        uint32_t aad = smem_u32(As + (size_t)(atr + mf * 16) * 72 + kk + atc);
        LDSM_X4(a[mf], aad);
      }
#pragma unroll
      for (int nh = 0; nh < 2; nh++) {
        uint32_t b[4];
        uint32_t bad1 = smem_u32(B1s + (size_t)(kk + btr) * 72 + btc + nh * 16);
        LDSM_X4T(b, bad1);
        mma16816(c1[0][nh * 2],     a[0], b);
        mma16816(c1[0][nh * 2 + 1], a[0], b + 2);
        mma16816(c1[1][nh * 2],     a[1], b);
        mma16816(c1[1][nh * 2 + 1], a[1], b + 2);
        uint32_t bad2 = smem_u32(B2s + (size_t)(kk + btr) * 72 + btc + nh * 16);
        LDSM_X4T(b, bad2);
        mma16816(c2[0][nh * 2],     a[0], b);
        mma16816(c2[0][nh * 2 + 1], a[0], b + 2);
        mma16816(c2[1][nh * 2],     a[1], b);
        mma16816(c2[1][nh * 2 + 1], a[1], b + 2);
      }
    }
  }

  const int grp = lane >> 2;
  const int qp  = (lane & 3) << 1;
#pragma unroll
  for (int mf = 0; mf < 2; mf++) {
#pragma unroll
    for (int nf = 0; nf < 4; nf++) {
#pragma unroll
      for (int h8 = 0; h8 < 2; h8++) {
        int rl = wm * 32 + mf * 16 + grp + h8 * 8;
        if (rl < nrows) {
          float h1a = c1[mf][nf][h8 * 2 + 0];
          float h1b = c1[mf][nf][h8 * 2 + 1];
          float h2a = c2[mf][nf][h8 * 2 + 0];
          float h2b = c2[mf][nf][h8 * 2 + 1];
          float ga = (h1a / (1.f + __expf(-h1a))) * h2a;
          float gb = (h1b / (1.f + __expf(-h1b))) * h2b;
          size_t o = (size_t)(row0 + rl) * I_DIM + (n0 + wn * 32 + nf * 8 + qp);
          *(__half2*)&g_gated[o] = __floats2half2_rn(ga, gb);
        }
      }
    }
  }
}

// ------------------- GEMM2: out += w * (gated * W3)  (fused combine) -------------------
__global__ __launch_bounds__(256, 2)
void gemm2_kernel(float* __restrict__ out) {
  int tile = blockIdx.y;
  if (tile >= g_ntiles) return;
  extern __shared__ char sm[];
  __shared__ int   tok_s[BM];
  __shared__ float w_s[BM];
  const int tid = threadIdx.x;
  const int e = g_tile_e[tile];
  const int row0 = g_tile_row[tile];
  const int nrows = g_tile_nrows[tile];
  const int n0 = blockIdx.x * 128;
  const __half* __restrict__ W3 = g_w3h + (size_t)e * I_DIM * D_DIM;

  if (tid < BM) {
    int r = row0 + tid;
    int rc = r < TRX ? r : TRX - 1;
    tok_s[tid] = g_perm_src[rc];
    w_s[tid] = g_wsort[rc];
  }

  const __half* ap[4];
  uint32_t ad[4];
#pragma unroll
  for (int q = 0; q < 4; q++) {
    int id = tid + q * 256;
    int r = id >> 3, cc = (id & 7) << 3;
    int srcr = row0 + r; if (srcr >= TRX) srcr = TRX - 1;
    ap[q] = g_gated + (size_t)srcr * I_DIM + cc;
    ad[q] = smem_u32(sm + G2_A) + (r * 72 + cc) * 2;
  }
  const __half* bp[4];
  uint32_t bd[4];
#pragma unroll
  for (int q = 0; q < 4; q++) {
    int id = tid + q * 256;
    int r = id >> 4, cc = (id & 15) << 3;
    bp[q] = W3 + (size_t)r * D_DIM + n0 + cc;
    bd[q] = smem_u32(sm + G2_B) + (r * 136 + cc) * 2;
  }

  float c[4][4][4];
#pragma unroll
  for (int i = 0; i < 4; i++)
#pragma unroll
    for (int j = 0; j < 4; j++)
#pragma unroll
      for (int q = 0; q < 4; q++) c[i][j][q] = 0.f;

  const int lane = tid & 31;
  const int wid = tid >> 5;
  const int wm = wid >> 2;
  const int wn = wid & 3;
  const int btr = (lane & 7) + ((lane >> 3) & 1) * 8;
  const int btc = wn * 32 + ((lane >> 4) << 3);
  const int atr = wm * 64 + (lane & 15);
  const int atc = (lane >> 4) << 3;

  const int NK = I_DIM / BK;  // 48
#pragma unroll
  for (int s = 0; s < STAGES - 1; s++) {
    int k0 = s * BK;
#pragma unroll
    for (int q = 0; q < 4; q++) CP_ASYNC16(ad[q] + s * A_ST, ap[q] + k0);
#pragma unroll
    for (int q = 0; q < 4; q++) CP_ASYNC16(bd[q] + s * B2_ST, bp[q] + (size_t)k0 * D_DIM);
    CP_COMMIT();
  }

#pragma unroll 1
  for (int it = 0; it < NK; it++) {
    const int buf = it % STAGES;
    CP_WAIT(STAGES - 2);
    __syncthreads();
    {
      int pf = it + STAGES - 1;
      if (pf < NK) {
        int sb = pf % STAGES;
        int k0 = pf * BK;
#pragma unroll
        for (int q = 0; q < 4; q++) CP_ASYNC16(ad[q] + sb * A_ST, ap[q] + k0);
#pragma unroll
        for (int q = 0; q < 4; q++) CP_ASYNC16(bd[q] + sb * B2_ST, bp[q] + (size_t)k0 * D_DIM);
      }
      CP_COMMIT();
    }
    const __half* As = (const __half*)(sm + G2_A + buf * A_ST);
    const __half* Bs = (const __half*)(sm + G2_B + buf * B2_ST);

#pragma unroll
    for (int kk = 0; kk < BK; kk += 16) {
      uint32_t a[4][4];
#pragma unroll
      for (int mf = 0; mf < 4; mf++) {
        uint32_t aad = smem_u32(As + (size_t)(atr + mf * 16) * 72 + kk + atc);
        LDSM_X4(a[mf], aad);
      }
#pragma unroll
      for (int nh = 0; nh < 2; nh++) {
        uint32_t b[4];
        uint32_t bad = smem_u32(Bs + (size_t)(kk + btr) * 136 + btc + nh * 16);
        LDSM_X4T(b, bad);
#pragma unroll
        for (int mf = 0; mf < 4; mf++) {
          mma16816(c[mf][nh * 2],     a[mf], b);
          mma16816(c[mf][nh * 2 + 1], a[mf], b + 2);
        }
      }
    }
  }

  const int grp = lane >> 2;
  const int qp  = (lane & 3) << 1;
#pragma unroll
  for (int mf = 0; mf < 4; mf++) {
#pragma unroll
    for (int h8 = 0; h8 < 2; h8++) {
      int rl = wm * 64 + mf * 16 + grp + h8 * 8;
      if (rl < nrows) {
        float w = w_s[rl];
        float* orow = out + (size_t)tok_s[rl] * D_DIM + n0 + wn * 32 + qp;
#pragma unroll
        for (int nf = 0; nf < 4; nf++) {
          REDADD(orow + nf * 8,     w * c[mf][nf][h8 * 2 + 0]);
          REDADD(orow + nf * 8 + 1, w * c[mf][nf][h8 * 2 + 1]);
        }
      }
    }
  }
}

// ------------------------------- launch -------------------------------
extern "C" void kernel_launch(void* const* d_in, const int* in_sizes, int n_in,
                              void* d_out, int out_size) {
  const float* x  = (const float*)d_in[0];
  const float* rw = (const float*)d_in[1];
  const float* w1 = (const float*)d_in[2];
  const float* w2 = (const float*)d_in[3];
  const float* w3 = (const float*)d_in[4];
  float* out = (float*)d_out;

  static cudaStream_t s2 = nullptr;
  static cudaEvent_t ev_fork = nullptr, ev_cvt12 = nullptr, ev_cvt3 = nullptr;
  if (s2 == nullptr) {
    cudaStreamCreateWithFlags(&s2, cudaStreamNonBlocking);
    cudaEventCreateWithFlags(&ev_fork,  cudaEventDisableTiming);
    cudaEventCreateWithFlags(&ev_cvt12, cudaEventDisableTiming);
    cudaEventCreateWithFlags(&ev_cvt3,  cudaEventDisableTiming);
    cudaFuncSetAttribute(gemm1_kernel, cudaFuncAttributeMaxDynamicSharedMemorySize, G1_SMEM);
    cudaFuncSetAttribute(gemm2_kernel, cudaFuncAttributeMaxDynamicSharedMemorySize, G2_SMEM);
  }

  // side stream: cvt1+cvt2 first (gates GEMM1), then zero_out+cvt3 (gate GEMM2,
  // hidden under GEMM1)
  cudaEventRecord(ev_fork, 0);
  cudaStreamWaitEvent(s2, ev_fork, 0);
  cvt_w_kernel<<<WBLK16, 256, 0, s2>>>(w1, 0);
  cvt_w_kernel<<<WBLK16, 256, 0, s2>>>(w2, 1);
  cudaEventRecord(ev_cvt12, s2);
  zero_out_kernel<<<T_TOK * D_DIM / 1024, 256, 0, s2>>>(out);
  cvt_w_kernel<<<WBLK16, 256, 0, s2>>>(w3, 2);
  cudaEventRecord(ev_cvt3, s2);

  // main stream: token pipeline
  zero_kernel<<<1, 32>>>();
  router_kernel<<<T_TOK / 8, 256>>>(x, rw);              // also writes g_xh
  scan_aux_kernel<<<1, 32>>>(out + (size_t)T_TOK * D_DIM);
  scatter_kernel<<<TRX / 256, 256>>>();

  cudaStreamWaitEvent(0, ev_cvt12, 0);                   // need w1h/w2h
  gemm1_kernel<<<dim3(I_DIM / 64, GRID_TILES), 256, G1_SMEM>>>();
  cudaStreamWaitEvent(0, ev_cvt3, 0);                    // need w3h + zeroed out
  gemm2_kernel<<<dim3(D_DIM / 128, GRID_TILES), 256, G2_SMEM>>>(out);
}